// round 1
// baseline (speedup 1.0000x reference)
#include <cuda_runtime.h>

// Problem constants
static constexpr int B_ = 4;
static constexpr int T_ = 1024;
static constexpr int C_ = 768;
static constexpr int H_ = 12;
static constexpr int D_ = 64;
static constexpr int C3 = 3 * C_;          // 2304

// Scratch (device globals; no allocations allowed)
__device__ float g_qkv[(size_t)B_ * T_ * C3];            // [B,T,3,H,D] packed as [B*T, 2304]
__device__ float g_logits[(size_t)B_ * H_ * T_ * T_];    // [B,H,T,T]
__device__ float g_y[(size_t)B_ * T_ * C_];              // [B,T,C] attention output pre-proj

// ---------------------------------------------------------------------------
// Generic batched tiled SGEMM: C = scale * A * op(B) (+ biasVec)(+ biasMat)(+ maskMat)
//   A: M x K row-major (lda), op(B): K x N.  TRANSB=false: B is KxN (ldb).
//   TRANSB=true: B is NxK row-major (ldb) and we compute A * B^T.
//   Batched over grid.z = bb*Hdim + hh with independent strides for b and h.
// Tile: 64x64, K-tile 16, 256 threads, 4x4 per-thread microtile.
// All dims assumed divisible (64 for M/N, 16 for K) -- true for this problem.
// ---------------------------------------------------------------------------
template <bool TRANSB>
__global__ __launch_bounds__(256) void gemm_kernel(
    const float* __restrict__ A, const float* __restrict__ Bm, float* __restrict__ Cm,
    const float* __restrict__ biasVec, const float* __restrict__ biasMat,
    const float* __restrict__ maskMat, float scale,
    int M, int N, int K, int lda, int ldb, int ldc,
    int Hdim,
    long sAb, long sAh, long sBb, long sBh, long sCb, long sCh,
    long sBMb, long sBMh, long sMb, int ldE)
{
    const int bz = blockIdx.z;
    const int bb = bz / Hdim;
    const int hh = bz - bb * Hdim;
    A  += bb * sAb + hh * sAh;
    Bm += bb * sBb + hh * sBh;
    Cm += bb * sCb + hh * sCh;
    if (biasMat) biasMat += bb * sBMb + hh * sBMh;
    if (maskMat) maskMat += bb * sMb;

    __shared__ float As[16][68];
    __shared__ float Bs[16][68];

    const int tid = threadIdx.x;
    const int m0 = blockIdx.y * 64;
    const int n0 = blockIdx.x * 64;

    const int tx = tid & 15;         // 0..15 -> n microtile
    const int ty = tid >> 4;         // 0..15 -> m microtile

    // loader indices
    const int la_m = tid >> 2;            // 0..63 (row of A tile, or row-n of B tile if TRANSB)
    const int la_k = (tid & 3) * 4;       // 0,4,8,12
    const int lb_k = tid >> 4;            // 0..15 (NN B loader)
    const int lb_n = (tid & 15) * 4;      // 0..60

    float acc[4][4] = {};

    for (int k0 = 0; k0 < K; k0 += 16) {
        // Load A tile (64 x 16) transposed into As[k][m]
        {
            float4 av = *(const float4*)(A + (long)(m0 + la_m) * lda + (k0 + la_k));
            As[la_k + 0][la_m] = av.x;
            As[la_k + 1][la_m] = av.y;
            As[la_k + 2][la_m] = av.z;
            As[la_k + 3][la_m] = av.w;
        }
        if (TRANSB) {
            // B is N x K; tile rows are n, cols are k. Store Bs[k][n].
            float4 bv = *(const float4*)(Bm + (long)(n0 + la_m) * ldb + (k0 + la_k));
            Bs[la_k + 0][la_m] = bv.x;
            Bs[la_k + 1][la_m] = bv.y;
            Bs[la_k + 2][la_m] = bv.z;
            Bs[la_k + 3][la_m] = bv.w;
        } else {
            float4 bv = *(const float4*)(Bm + (long)(k0 + lb_k) * ldb + (n0 + lb_n));
            *(float4*)&Bs[lb_k][lb_n] = bv;
        }
        __syncthreads();

        #pragma unroll
        for (int kk = 0; kk < 16; kk++) {
            float4 a4 = *(const float4*)&As[kk][ty * 4];
            float4 b4 = *(const float4*)&Bs[kk][tx * 4];
            float a[4] = {a4.x, a4.y, a4.z, a4.w};
            float b[4] = {b4.x, b4.y, b4.z, b4.w};
            #pragma unroll
            for (int i = 0; i < 4; i++)
                #pragma unroll
                for (int j = 0; j < 4; j++)
                    acc[i][j] += a[i] * b[j];
        }
        __syncthreads();
    }

    // Epilogue
    #pragma unroll
    for (int i = 0; i < 4; i++) {
        const long m = m0 + ty * 4 + i;
        const long n = n0 + tx * 4;
        float4 r;
        r.x = acc[i][0] * scale;
        r.y = acc[i][1] * scale;
        r.z = acc[i][2] * scale;
        r.w = acc[i][3] * scale;
        if (biasVec) {
            float4 bv = *(const float4*)(biasVec + n);
            r.x += bv.x; r.y += bv.y; r.z += bv.z; r.w += bv.w;
        }
        if (biasMat) {
            float4 bm = *(const float4*)(biasMat + m * ldE + n);
            r.x += bm.x; r.y += bm.y; r.z += bm.z; r.w += bm.w;
        }
        if (maskMat) {
            float4 mk = *(const float4*)(maskMat + m * ldE + n);
            r.x += mk.x; r.y += mk.y; r.z += mk.z; r.w += mk.w;
        }
        *(float4*)(Cm + m * ldc + n) = r;
    }
}

// ---------------------------------------------------------------------------
// Row softmax over 1024-wide rows. One block (256 threads) per row; each
// thread owns exactly one float4.
// ---------------------------------------------------------------------------
__global__ __launch_bounds__(256) void softmax_kernel(const float* __restrict__ in,
                                                      float* __restrict__ out)
{
    const long row = blockIdx.x;
    const float4* ip = (const float4*)(in + row * 1024);
    float4* op = (float4*)(out + row * 1024);
    const int tid = threadIdx.x;
    __shared__ float sred[8];

    float4 v = ip[tid];
    float m = fmaxf(fmaxf(v.x, v.y), fmaxf(v.z, v.w));
    #pragma unroll
    for (int o = 16; o; o >>= 1) m = fmaxf(m, __shfl_xor_sync(0xffffffffu, m, o));
    if ((tid & 31) == 0) sred[tid >> 5] = m;
    __syncthreads();
    float gm = sred[0];
    #pragma unroll
    for (int i = 1; i < 8; i++) gm = fmaxf(gm, sred[i]);
    __syncthreads();

    v.x = __expf(v.x - gm);
    v.y = __expf(v.y - gm);
    v.z = __expf(v.z - gm);
    v.w = __expf(v.w - gm);
    float s = v.x + v.y + v.z + v.w;
    #pragma unroll
    for (int o = 16; o; o >>= 1) s += __shfl_xor_sync(0xffffffffu, s, o);
    if ((tid & 31) == 0) sred[tid >> 5] = s;
    __syncthreads();
    float gs = sred[0];
    #pragma unroll
    for (int i = 1; i < 8; i++) gs += sred[i];

    const float inv = 1.0f / gs;
    v.x *= inv; v.y *= inv; v.z *= inv; v.w *= inv;
    op[tid] = v;
}

// ---------------------------------------------------------------------------
// Launch: qkv GEMM -> QK^T(+scale+bias+mask) -> softmax -> AV -> proj
// ---------------------------------------------------------------------------
extern "C" void kernel_launch(void* const* d_in, const int* in_sizes, int n_in,
                              void* d_out, int out_size)
{
    const float* x     = (const float*)d_in[0];
    const float* mask  = (const float*)d_in[1];
    const float* bias  = (const float*)d_in[2];
    const float* Wqkv  = (const float*)d_in[3];
    const float* bqkv  = (const float*)d_in[4];
    const float* Wproj = (const float*)d_in[5];
    const float* bproj = (const float*)d_in[6];
    float* out = (float*)d_out;

    float *qkv, *logits, *y;
    cudaGetSymbolAddress((void**)&qkv,    g_qkv);
    cudaGetSymbolAddress((void**)&logits, g_logits);
    cudaGetSymbolAddress((void**)&y,      g_y);

    const long YN = (long)B_ * T_ * C_;
    const long AN = (long)B_ * H_ * T_ * T_;
    float* attn = ((long)out_size >= YN + AN) ? (out + YN) : logits;

    dim3 blk(256);

    // 1) qkv = x @ W_qkv + b_qkv        [4096 x 2304], K=768
    gemm_kernel<false><<<dim3(C3 / 64, (B_ * T_) / 64, 1), blk>>>(
        x, Wqkv, qkv, bqkv, nullptr, nullptr, 1.0f,
        B_ * T_, C3, C_, C_, C3, C3,
        1, 0, 0, 0, 0, 0, 0, 0, 0, 0, 0);

    // 2) logits = scale * q @ k^T + bias + mask   batched over (b,h)
    gemm_kernel<true><<<dim3(T_ / 64, T_ / 64, B_ * H_), blk>>>(
        qkv /*q base*/, qkv + C_ /*k base*/, logits,
        nullptr, bias, mask, 0.125f,
        T_, T_, D_, C3, C3, T_,
        H_,
        (long)T_ * C3, (long)D_,            // A (q) strides: b, h
        (long)T_ * C3, (long)D_,            // B (k) strides: b, h
        (long)H_ * T_ * T_, (long)T_ * T_,  // C (logits) strides: b, h
        (long)H_ * T_ * T_, (long)T_ * T_,  // biasMat strides: b, h
        (long)T_ * T_,                      // mask stride: b only
        T_);

    // 3) attn = softmax(logits) rows; written straight to d_out region if present
    softmax_kernel<<<B_ * H_ * T_, 256>>>(logits, attn);

    // 4) y[b,t,h*D+d] = attn @ v        batched over (b,h), N=64, K=1024
    gemm_kernel<false><<<dim3(1, T_ / 64, B_ * H_), blk>>>(
        attn, qkv + 2 * C_ /*v base*/, y, nullptr, nullptr, nullptr, 1.0f,
        T_, D_, T_, T_, C3, C_,
        H_,
        (long)H_ * T_ * T_, (long)T_ * T_,  // A (attn) strides: b, h
        (long)T_ * C3, (long)D_,            // B (v) strides: b, h
        (long)T_ * C_, (long)D_,            // C (y) strides: b, h
        0, 0, 0, 0);

    // 5) out = y @ W_proj + b_proj      [4096 x 768], K=768
    gemm_kernel<false><<<dim3(C_ / 64, (B_ * T_) / 64, 1), blk>>>(
        y, Wproj, out, bproj, nullptr, nullptr, 1.0f,
        B_ * T_, C_, C_, C_, C_, C_,
        1, 0, 0, 0, 0, 0, 0, 0, 0, 0, 0);
}